// round 15
// baseline (speedup 1.0000x reference)
#include <cuda_runtime.h>
#include <cuda_fp16.h>
#include <math.h>
#include <stdint.h>

#define N_NODES 20000
#define N_EDGES 320000
#define EDGE_BLK 625   // 625 * 256 * 2 == N_EDGES

// ---------------- device scratch ----------------
__device__ int   g_cnt[N_NODES];       // zero at load; re-zeroed by scan each call
__device__ int   g_ptr[N_NODES + 1];
__device__ int   g_cur[N_NODES];
__device__ __align__(16) int2  g_srcw[N_EDGES];
__device__ float g_deg[N_NODES];
__device__ float g_dinv[N_NODES];
__device__ __align__(256) __half g_aggh[N_NODES * 256];
__device__ __align__(256) __half g_featA[N_NODES * 256];
__device__ __align__(256) __half g_featB[N_NODES * 128];
__device__ __align__(16) __half g_w1h[32 * 64];
__device__ __align__(16) __half g_w2h[64 * 128];
__device__ __align__(16) __half g_w3h[128 * 256];
__device__ __align__(16) __half g_w4h[256 * 512];
__device__ float g_hpart[8 * N_NODES];
__device__ float g_h[N_NODES];

// ---------------- helpers ----------------
__device__ __forceinline__ bool detect64(const void* e) {
    const long long* p = (const long long*)e;
    bool ok = true;
#pragma unroll
    for (int k = 0; k < 8; k++) {
        long long v = p[k];
        if (v < 0 || v >= N_NODES) ok = false;
    }
    return ok;
}
__device__ __forceinline__ int edge_at2(const void* e, long long idx, bool e64) {
    if (e64) return (int)((const long long*)e)[idx];
    return ((const int*)e)[idx];
}

// ---------------- fused histogram + weight conversion ----------------
__global__ void histo_prep_kernel(const void* e, const float* __restrict__ W1,
                                  const float* __restrict__ W2, const float* __restrict__ W3,
                                  const float* __restrict__ W4) {
    int b = blockIdx.x, t = threadIdx.x;
    if (b < EDGE_BLK) {
        bool e64 = detect64(e);
        int i0 = (b * 256 + t) * 2;
        int d0 = edge_at2(e, (long long)N_EDGES + i0, e64);
        int d1 = edge_at2(e, (long long)N_EDGES + i0 + 1, e64);
        atomicAdd(&g_cnt[d0], 1);
        atomicAdd(&g_cnt[d1], 1);
    } else {
        int i = (b - EDGE_BLK) * 256 + t;   // [0, 174080)
        if (i < 2048) {
            int k = i >> 6, n = i & 63;
            g_w1h[i] = __float2half(k < 16 ? W1[k * 64 + n] : 0.f);
        } else if (i < 10240) {
            int j = i - 2048;  g_w2h[j] = __float2half(W2[j]);
        } else if (i < 43008) {
            int j = i - 10240; g_w3h[j] = __float2half(W3[j]);
        } else if (i < 174080) {
            int j = i - 43008; g_w4h[j] = __float2half(W4[j]);
        }
    }
}

// ---------------- single-block scan + node init (re-zeros g_cnt) ----------------
__global__ void scan_node_init_kernel() {
    const int C = (N_NODES + 1023) / 1024;   // 20
    int t = threadIdx.x;
    int base = t * C;
    int local[C];
    int sum = 0;
#pragma unroll
    for (int c = 0; c < C; c++) {
        int i = base + c;
        int v = (i < N_NODES) ? g_cnt[i] : 0;
        sum += v;
        local[c] = sum;
    }
    int lane = t & 31, wid = t >> 5;
    int incl = sum;
#pragma unroll
    for (int o = 1; o < 32; o <<= 1) {
        int y = __shfl_up_sync(0xffffffffu, incl, o);
        if (lane >= o) incl += y;
    }
    __shared__ int ws[32];
    if (lane == 31) ws[wid] = incl;
    __syncthreads();
    if (wid == 0) {
        int v = ws[lane];
        int iv = v;
#pragma unroll
        for (int o = 1; o < 32; o <<= 1) {
            int y = __shfl_up_sync(0xffffffffu, iv, o);
            if (lane >= o) iv += y;
        }
        ws[lane] = iv - v;
    }
    __syncthreads();
    int offset = ws[wid] + (incl - sum);
    if (t == 0) g_ptr[0] = 0;
#pragma unroll
    for (int c = 0; c < C; c++) {
        int i = base + c;
        if (i >= N_NODES) break;
        g_ptr[i + 1] = offset + local[c];
        g_cur[i] = offset + (c ? local[c - 1] : 0);
        int v = local[c] - (c ? local[c - 1] : 0);
        float d = (float)(v + 1);
        g_deg[i] = d;
        g_dinv[i] = rsqrtf(d);
        g_cnt[i] = 0;   // restore for next graph replay
    }
}

__global__ void fill_kernel(const void* e) {
    bool e64 = detect64(e);
    int i0 = (blockIdx.x * blockDim.x + threadIdx.x) * 2;
    int s0 = edge_at2(e, i0, e64);
    int d0 = edge_at2(e, (long long)N_EDGES + i0, e64);
    int s1 = edge_at2(e, i0 + 1, e64);
    int d1 = edge_at2(e, (long long)N_EDGES + i0 + 1, e64);
    int p0 = atomicAdd(&g_cur[d0], 1);
    int p1 = atomicAdd(&g_cur[d1], 1);
    g_srcw[p0] = make_int2(s0, __float_as_int(g_dinv[s0]));
    g_srcw[p1] = make_int2(s1, __float_as_int(g_dinv[s1]));
}

// ---------------- aggregation (warp per node, fp16 features, 4x MLP) ----------------
template <int D>
__global__ void aggregate_half_kernel(const __half* __restrict__ X, __half* __restrict__ A) {
    int node = (blockIdx.x * blockDim.x + threadIdx.x) >> 5;
    int lane = threadIdx.x & 31;
    if (node >= N_NODES) return;
    int beg = g_ptr[node], end = g_ptr[node + 1];
    float di = g_dinv[node];
    float selfw = di * di;
    float scale = 1.0f / g_deg[node];
    constexpr int V2 = D / 64;

    float2 acc[V2];
#pragma unroll
    for (int r = 0; r < V2; r++) acc[r] = make_float2(0.f, 0.f);

    auto rowptr = [&](int src) {
        return (const __half2*)(X + (long long)src * D) + lane * V2;
    };
    auto accum = [&](const __half2* hp, float w) {
#pragma unroll
        for (int r = 0; r < V2; r++) {
            float2 v = __half22float2(hp[r]);
            acc[r].x += w * v.x; acc[r].y += w * v.y;
        }
    };

    int p = beg;
    int end4 = beg + ((end - beg) & ~3);
    for (; p < end4; p += 4) {
        int2 sw0 = g_srcw[p], sw1 = g_srcw[p + 1], sw2 = g_srcw[p + 2], sw3 = g_srcw[p + 3];
        if constexpr (V2 == 4) {
            uint4 r0 = *(const uint4*)rowptr(sw0.x);
            uint4 r1 = *(const uint4*)rowptr(sw1.x);
            uint4 r2 = *(const uint4*)rowptr(sw2.x);
            uint4 r3 = *(const uint4*)rowptr(sw3.x);
            accum((const __half2*)&r0, __int_as_float(sw0.y));
            accum((const __half2*)&r1, __int_as_float(sw1.y));
            accum((const __half2*)&r2, __int_as_float(sw2.y));
            accum((const __half2*)&r3, __int_as_float(sw3.y));
        } else if constexpr (V2 == 2) {
            uint2 r0 = *(const uint2*)rowptr(sw0.x);
            uint2 r1 = *(const uint2*)rowptr(sw1.x);
            uint2 r2 = *(const uint2*)rowptr(sw2.x);
            uint2 r3 = *(const uint2*)rowptr(sw3.x);
            accum((const __half2*)&r0, __int_as_float(sw0.y));
            accum((const __half2*)&r1, __int_as_float(sw1.y));
            accum((const __half2*)&r2, __int_as_float(sw2.y));
            accum((const __half2*)&r3, __int_as_float(sw3.y));
        } else {
            __half2 r0 = *rowptr(sw0.x), r1 = *rowptr(sw1.x);
            __half2 r2 = *rowptr(sw2.x), r3 = *rowptr(sw3.x);
            accum(&r0, __int_as_float(sw0.y));
            accum(&r1, __int_as_float(sw1.y));
            accum(&r2, __int_as_float(sw2.y));
            accum(&r3, __int_as_float(sw3.y));
        }
    }
    for (; p < end; p++) {
        int2 sw = g_srcw[p];
        if constexpr (V2 == 4) {
            uint4 r0 = *(const uint4*)rowptr(sw.x);
            accum((const __half2*)&r0, __int_as_float(sw.y));
        } else if constexpr (V2 == 2) {
            uint2 r0 = *(const uint2*)rowptr(sw.x);
            accum((const __half2*)&r0, __int_as_float(sw.y));
        } else {
            __half2 r0 = *rowptr(sw.x);
            accum(&r0, __int_as_float(sw.y));
        }
    }

    const __half2* xi = (const __half2*)(X + (long long)node * D) + lane * V2;
    __half2* ao = (__half2*)(A + (long long)node * D) + lane * V2;
#pragma unroll
    for (int r = 0; r < V2; r++) {
        float2 s = __half22float2(xi[r]);
        ao[r] = __floats2half2_rn((di * acc[r].x + selfw * s.x) * scale,
                                  (di * acc[r].y + selfw * s.y) * scale);
    }
}

__global__ void aggregate16_kernel(const float* __restrict__ X, __half* __restrict__ A) {
    int node = (blockIdx.x * blockDim.x + threadIdx.x) >> 5;
    int lane = threadIdx.x & 31;
    if (node >= N_NODES) return;
    int beg = g_ptr[node], end = g_ptr[node + 1];
    float di = g_dinv[node];
    float acc = 0.f;
    int lidx = lane & 15;
    int p = beg;
    int end4 = beg + ((end - beg) & ~3);
    for (; p < end4; p += 4) {
        int2 sw0 = g_srcw[p], sw1 = g_srcw[p + 1], sw2 = g_srcw[p + 2], sw3 = g_srcw[p + 3];
        float v0 = X[(long long)sw0.x * 16 + lidx];
        float v1 = X[(long long)sw1.x * 16 + lidx];
        float v2 = X[(long long)sw2.x * 16 + lidx];
        float v3 = X[(long long)sw3.x * 16 + lidx];
        acc += __int_as_float(sw0.y) * v0 + __int_as_float(sw1.y) * v1
             + __int_as_float(sw2.y) * v2 + __int_as_float(sw3.y) * v3;
    }
    for (; p < end; p++) {
        int2 sw = g_srcw[p];
        acc += __int_as_float(sw.y) * X[(long long)sw.x * 16 + lidx];
    }
    acc = (di * acc + di * di * X[(long long)node * 16 + lidx]) / g_deg[node];
    A[(long long)node * 32 + lane] = __float2half(lane < 16 ? acc : 0.f);
}

// ---------------- fp16 tensor-core GEMM (HMMA m16n8k16, cp.async, ldmatrix) ----------------
__device__ __forceinline__ void mma_f16(float& c0, float& c1, float& c2, float& c3,
                                        uint32_t a0, uint32_t a1, uint32_t a2, uint32_t a3,
                                        uint32_t b0, uint32_t b1) {
    asm volatile(
        "mma.sync.aligned.m16n8k16.row.col.f32.f16.f16.f32 "
        "{%0,%1,%2,%3},{%4,%5,%6,%7},{%8,%9},{%0,%1,%2,%3};\n"
        : "+f"(c0), "+f"(c1), "+f"(c2), "+f"(c3)
        : "r"(a0), "r"(a1), "r"(a2), "r"(a3), "r"(b0), "r"(b1));
}

__device__ __forceinline__ void ldsm_x4(uint32_t& r0, uint32_t& r1, uint32_t& r2, uint32_t& r3,
                                        uint32_t addr) {
    asm volatile("ldmatrix.sync.aligned.m8n8.x4.shared.b16 {%0,%1,%2,%3}, [%4];"
                 : "=r"(r0), "=r"(r1), "=r"(r2), "=r"(r3) : "r"(addr));
}

__device__ __forceinline__ void ldsm_x4t(uint32_t& r0, uint32_t& r1, uint32_t& r2, uint32_t& r3,
                                         uint32_t addr) {
    asm volatile("ldmatrix.sync.aligned.m8n8.x4.trans.shared.b16 {%0,%1,%2,%3}, [%4];"
                 : "=r"(r0), "=r"(r1), "=r"(r2), "=r"(r3) : "r"(addr));
}

__device__ __forceinline__ void cp16(uint32_t dst, const void* src, bool pred) {
    int bytes = pred ? 16 : 0;
    asm volatile("cp.async.ca.shared.global [%0], [%1], 16, %2;\n"
                 :: "r"(dst), "l"(src), "r"(bytes));
}

// MODE: 1 = fp16 C, 2 = fused rowdot (no C)
template <int BN, int MODE>
__global__ __launch_bounds__(256)
void gemm_f16_kernel(const __half* __restrict__ A, const __half* __restrict__ B,
                     const float* __restrict__ bias, __half* __restrict__ Ch,
                     const float* __restrict__ w5, float* __restrict__ hpart,
                     int M, int K, int N) {
    constexpr int BM = 128, BK = 32;
    constexpr int ASTR = BK + 8;
    constexpr int BSTR = BN + 8;
    constexpr int WN = BN / 64, WM = 8 / WN, MT = BM / (WM * 16);

    __shared__ __half Ah[2][BM][ASTR];
    __shared__ __half Bh[2][BK][BSTR];

    int tid = threadIdx.x, lane = tid & 31, warp = tid >> 5;
    int warp_m = warp % WM, warp_n = warp / WM;
    int row0 = warp_m * (MT * 16), col0 = warp_n * 64;
    int rowBase = blockIdx.y * BM, colBase = blockIdx.x * BN;

    int ar = tid >> 2;
    int ac = (tid & 3) * 8;
    int br = tid / (BN / 8);
    int bc = (tid % (BN / 8)) * 8;

    auto issue = [&](int kt, int s) {
        int k0 = kt * BK;
#pragma unroll
        for (int i = 0; i < 2; i++) {
            int r = ar + i * 64;
            int gr = rowBase + r;
            bool ok = gr < M;
            const __half* src = A + (long long)(ok ? gr : 0) * K + k0 + ac;
            cp16((uint32_t)__cvta_generic_to_shared(&Ah[s][r][ac]), src, ok);
        }
        constexpr int RPW = 2048 / BN;
#pragma unroll
        for (int i = 0; i < BK / RPW; i++) {
            int r = br + i * RPW;
            const __half* src = B + (long long)(k0 + r) * N + colBase + bc;
            cp16((uint32_t)__cvta_generic_to_shared(&Bh[s][r][bc]), src, true);
        }
        asm volatile("cp.async.commit_group;\n");
    };

    float acc[MT][8][4];
#pragma unroll
    for (int mt = 0; mt < MT; mt++)
#pragma unroll
        for (int nt = 0; nt < 8; nt++)
#pragma unroll
            for (int q = 0; q < 4; q++) acc[mt][nt][q] = 0.f;

    int lr = lane >> 2, lc = lane & 3;
    int l8 = lane & 7;
    int lhalf = (lane >> 3) & 1;
    int lhi = lane >> 4;
    int KT = K / BK;

    issue(0, 0);
    for (int kt = 0; kt < KT; kt++) {
        int s = kt & 1;
        if (kt + 1 < KT) {
            issue(kt + 1, 1 - s);
            asm volatile("cp.async.wait_group 1;\n");
        } else {
            asm volatile("cp.async.wait_group 0;\n");
        }
        __syncthreads();
#pragma unroll
        for (int ks = 0; ks < 2; ks++) {
            int k16 = ks * 16;
            uint32_t bb[8][2];
#pragma unroll
            for (int pr = 0; pr < 4; pr++) {
                int n0 = col0 + pr * 16;
                uint32_t addr = (uint32_t)__cvta_generic_to_shared(
                    &Bh[s][k16 + l8 + lhalf * 8][n0 + lhi * 8]);
                ldsm_x4t(bb[2 * pr][0], bb[2 * pr][1], bb[2 * pr + 1][0], bb[2 * pr + 1][1], addr);
            }
#pragma unroll
            for (int mt = 0; mt < MT; mt++) {
                uint32_t a0, a1, a2, a3;
                uint32_t addr = (uint32_t)__cvta_generic_to_shared(
                    &Ah[s][row0 + mt * 16 + l8 + lhalf * 8][k16 + lhi * 8]);
                ldsm_x4(a0, a1, a2, a3, addr);
#pragma unroll
                for (int nt = 0; nt < 8; nt++)
                    mma_f16(acc[mt][nt][0], acc[mt][nt][1], acc[mt][nt][2], acc[mt][nt][3],
                            a0, a1, a2, a3, bb[nt][0], bb[nt][1]);
            }
        }
        __syncthreads();
    }

#pragma unroll
    for (int mt = 0; mt < MT; mt++) {
        int r1 = rowBase + row0 + mt * 16 + lr;
        int r2 = r1 + 8;
        float d1 = 0.f, d2 = 0.f;
#pragma unroll
        for (int nt = 0; nt < 8; nt++) {
            int c = colBase + col0 + nt * 8 + lc * 2;
            float bv0 = bias[c], bv1 = bias[c + 1];
            float v0 = fmaxf(acc[mt][nt][0] + bv0, 0.f);
            float v1 = fmaxf(acc[mt][nt][1] + bv1, 0.f);
            float v2 = fmaxf(acc[mt][nt][2] + bv0, 0.f);
            float v3 = fmaxf(acc[mt][nt][3] + bv1, 0.f);
            if constexpr (MODE == 2) {
                float w0 = w5[c], w1 = w5[c + 1];
                if (r1 < M) d1 += v0 * w0 + v1 * w1;
                if (r2 < M) d2 += v2 * w0 + v3 * w1;
            } else {
                if (r1 < M) *(__half2*)(Ch + (long long)r1 * N + c) = __floats2half2_rn(v0, v1);
                if (r2 < M) *(__half2*)(Ch + (long long)r2 * N + c) = __floats2half2_rn(v2, v3);
            }
        }
        if constexpr (MODE == 2) {
            d1 += __shfl_xor_sync(0xffffffffu, d1, 1);
            d1 += __shfl_xor_sync(0xffffffffu, d1, 2);
            d2 += __shfl_xor_sync(0xffffffffu, d2, 1);
            d2 += __shfl_xor_sync(0xffffffffu, d2, 2);
            int slot = blockIdx.x * WN + warp_n;
            if (lc == 0) {
                if (r1 < M) hpart[slot * N_NODES + r1] = d1;
                if (r2 < M) hpart[slot * N_NODES + r2] = d2;
            }
        }
    }
}

// ---------------- layer-5 reduce + add-aggregate + sigmoid ----------------
__global__ void hreduce_kernel(const float* __restrict__ hpart, float* __restrict__ h) {
    int i = blockIdx.x * blockDim.x + threadIdx.x;
    if (i < N_NODES) {
        float s = 0.f;
#pragma unroll
        for (int j = 0; j < 8; j++) s += hpart[j * N_NODES + i];
        h[i] = s;
    }
}

__global__ void final_agg_kernel(const float* __restrict__ h, const float* __restrict__ b5,
                                 float* __restrict__ out) {
    int i = blockIdx.x * blockDim.x + threadIdx.x;
    if (i >= N_NODES) return;
    float s = 0.f;
    int beg = g_ptr[i], end = g_ptr[i + 1];
    int p = beg;
    int end4 = beg + ((end - beg) & ~3);
    for (; p < end4; p += 4) {
        int2 sw0 = g_srcw[p], sw1 = g_srcw[p + 1], sw2 = g_srcw[p + 2], sw3 = g_srcw[p + 3];
        float h0 = h[sw0.x], h1 = h[sw1.x], h2 = h[sw2.x], h3 = h[sw3.x];
        s += __int_as_float(sw0.y) * h0 + __int_as_float(sw1.y) * h1
           + __int_as_float(sw2.y) * h2 + __int_as_float(sw3.y) * h3;
    }
    for (; p < end; p++) {
        int2 sw = g_srcw[p];
        s += __int_as_float(sw.y) * h[sw.x];
    }
    float di = g_dinv[i];
    float v = di * s + di * di * h[i] + b5[0];
    out[i] = 1.f / (1.f + expf(-v));
}

// ---------------- launch ----------------
extern "C" void kernel_launch(void* const* d_in, const int* in_sizes, int n_in,
                              void* d_out, int out_size) {
    const float* x  = (const float*)d_in[0];
    const void*  ei = d_in[1];
    const float* W1 = (const float*)d_in[2],  *b1 = (const float*)d_in[3];
    const float* W2 = (const float*)d_in[4],  *b2 = (const float*)d_in[5];
    const float* W3 = (const float*)d_in[6],  *b3 = (const float*)d_in[7];
    const float* W4 = (const float*)d_in[8],  *b4 = (const float*)d_in[9];
    const float* W5 = (const float*)d_in[10], *b5 = (const float*)d_in[11];
    float* out = (float*)d_out;

    __half *aggh, *featA, *featB, *w1h, *w2h, *w3h, *w4h;
    float *hpart, *hbuf;
    cudaGetSymbolAddress((void**)&aggh,  g_aggh);
    cudaGetSymbolAddress((void**)&featA, g_featA);
    cudaGetSymbolAddress((void**)&featB, g_featB);
    cudaGetSymbolAddress((void**)&w1h,   g_w1h);
    cudaGetSymbolAddress((void**)&w2h,   g_w2h);
    cudaGetSymbolAddress((void**)&w3h,   g_w3h);
    cudaGetSymbolAddress((void**)&w4h,   g_w4h);
    cudaGetSymbolAddress((void**)&hpart, g_hpart);
    cudaGetSymbolAddress((void**)&hbuf,  g_h);

    const int TPB = 256;
    int nodeBlocks = (N_NODES + TPB - 1) / TPB;
    int warpNodeBlocks = (N_NODES * 32 + TPB - 1) / TPB;
    int mBlocks = (N_NODES + 127) / 128;

    histo_prep_kernel<<<EDGE_BLK + 680, TPB>>>(ei, W1, W2, W3, W4);
    scan_node_init_kernel<<<1, 1024>>>();
    fill_kernel<<<EDGE_BLK, TPB>>>(ei);

    aggregate16_kernel<<<warpNodeBlocks, TPB>>>(x, aggh);
    gemm_f16_kernel<64, 1><<<dim3(1, mBlocks), 256>>>(aggh, w1h, b1, featA, nullptr, nullptr,
                                                      N_NODES, 32, 64);
    aggregate_half_kernel<64><<<warpNodeBlocks, TPB>>>(featA, aggh);
    gemm_f16_kernel<128, 1><<<dim3(1, mBlocks), 256>>>(aggh, w2h, b2, featB, nullptr, nullptr,
                                                       N_NODES, 64, 128);
    aggregate_half_kernel<128><<<warpNodeBlocks, TPB>>>(featB, aggh);
    gemm_f16_kernel<128, 1><<<dim3(2, mBlocks), 256>>>(aggh, w3h, b3, featA, nullptr, nullptr,
                                                       N_NODES, 128, 256);
    aggregate_half_kernel<256><<<warpNodeBlocks, TPB>>>(featA, aggh);
    gemm_f16_kernel<128, 2><<<dim3(4, mBlocks), 256>>>(aggh, w4h, b4, nullptr, W5, hpart,
                                                       N_NODES, 256, 512);
    hreduce_kernel<<<nodeBlocks, TPB>>>(hpart, hbuf);
    final_agg_kernel<<<nodeBlocks, TPB>>>(hbuf, b5, out);
}

// round 16
// speedup vs baseline: 1.0665x; 1.0665x over previous
#include <cuda_runtime.h>
#include <cuda_fp16.h>
#include <math.h>
#include <stdint.h>

#define N_NODES 20000
#define N_EDGES 320000

// ---------------- device scratch ----------------
__device__ int   g_e64;
__device__ int   g_cnt[N_NODES];
__device__ int   g_ptr[N_NODES + 1];
__device__ int   g_cur[N_NODES];
__device__ __align__(16) int2  g_srcw[N_EDGES];
__device__ float g_deg[N_NODES];
__device__ float g_dinv[N_NODES];
__device__ __align__(256) __half g_aggh[N_NODES * 256];
__device__ __align__(256) __half g_featA[N_NODES * 256];
__device__ __align__(256) __half g_featB[N_NODES * 128];
__device__ __align__(16) __half g_w1h[32 * 64];
__device__ __align__(16) __half g_w2h[64 * 128];
__device__ __align__(16) __half g_w3h[128 * 256];
__device__ __align__(16) __half g_w4h[256 * 512];
__device__ float g_hpart[8 * N_NODES];
__device__ float g_h[N_NODES];

__device__ __forceinline__ int edge_at(const void* e, long long idx) {
    if (g_e64) return (int)((const long long*)e)[idx];
    return ((const int*)e)[idx];
}

// ---------------- prep: zero cnt + dtype detect + weight fp16 conversion ----------------
__global__ void prep_kernel(const void* e, const float* __restrict__ W1,
                            const float* __restrict__ W2, const float* __restrict__ W3,
                            const float* __restrict__ W4) {
    int i = blockIdx.x * blockDim.x + threadIdx.x;
    if (i < N_NODES) g_cnt[i] = 0;
    if (i == 0) {
        const long long* p = (const long long*)e;
        bool ok = true;
#pragma unroll
        for (int k = 0; k < 8; k++) {
            long long v = p[k];
            if (v < 0 || v >= N_NODES) ok = false;
        }
        g_e64 = ok ? 1 : 0;
    }
    if (i < 2048) {
        int k = i >> 6, n = i & 63;
        g_w1h[i] = __float2half(k < 16 ? W1[k * 64 + n] : 0.f);
    } else if (i < 2048 + 8192) {
        int j = i - 2048;  g_w2h[j] = __float2half(W2[j]);
    } else if (i < 2048 + 8192 + 32768) {
        int j = i - 10240; g_w3h[j] = __float2half(W3[j]);
    } else if (i < 2048 + 8192 + 32768 + 131072) {
        int j = i - 43008; g_w4h[j] = __float2half(W4[j]);
    }
}

__global__ void histo_kernel(const void* e) {
    int i0 = (blockIdx.x * blockDim.x + threadIdx.x) * 2;
    int d0 = -1, d1 = -1;
    if (i0 < N_EDGES)     d0 = edge_at(e, (long long)N_EDGES + i0);
    if (i0 + 1 < N_EDGES) d1 = edge_at(e, (long long)N_EDGES + i0 + 1);
    if (d0 >= 0) atomicAdd(&g_cnt[d0], 1);
    if (d1 >= 0) atomicAdd(&g_cnt[d1], 1);
}

__global__ void scan_node_init_kernel() {
    const int C = (N_NODES + 1023) / 1024;   // 20
    int t = threadIdx.x;
    int base = t * C;
    int local[C];
    int sum = 0;
#pragma unroll
    for (int c = 0; c < C; c++) {
        int i = base + c;
        int v = (i < N_NODES) ? g_cnt[i] : 0;
        sum += v;
        local[c] = sum;
    }
    int lane = t & 31, wid = t >> 5;
    int incl = sum;
#pragma unroll
    for (int o = 1; o < 32; o <<= 1) {
        int y = __shfl_up_sync(0xffffffffu, incl, o);
        if (lane >= o) incl += y;
    }
    __shared__ int ws[32];
    if (lane == 31) ws[wid] = incl;
    __syncthreads();
    if (wid == 0) {
        int v = ws[lane];
        int iv = v;
#pragma unroll
        for (int o = 1; o < 32; o <<= 1) {
            int y = __shfl_up_sync(0xffffffffu, iv, o);
            if (lane >= o) iv += y;
        }
        ws[lane] = iv - v;
    }
    __syncthreads();
    int offset = ws[wid] + (incl - sum);
    if (t == 0) g_ptr[0] = 0;
#pragma unroll
    for (int c = 0; c < C; c++) {
        int i = base + c;
        if (i >= N_NODES) break;
        g_ptr[i + 1] = offset + local[c];
        g_cur[i] = offset + (c ? local[c - 1] : 0);
        int v = local[c] - (c ? local[c - 1] : 0);
        float d = (float)(v + 1);
        g_deg[i] = d;
        g_dinv[i] = rsqrtf(d);
    }
}

__global__ void fill_kernel(const void* e) {
    int i0 = (blockIdx.x * blockDim.x + threadIdx.x) * 2;
    int s0 = 0, s1 = 0, p0 = -1, p1 = -1;
    if (i0 < N_EDGES) {
        s0 = edge_at(e, i0);
        int d0 = edge_at(e, (long long)N_EDGES + i0);
        p0 = atomicAdd(&g_cur[d0], 1);
    }
    if (i0 + 1 < N_EDGES) {
        s1 = edge_at(e, i0 + 1);
        int d1 = edge_at(e, (long long)N_EDGES + i0 + 1);
        p1 = atomicAdd(&g_cur[d1], 1);
    }
    if (p0 >= 0) g_srcw[p0] = make_int2(s0, __float_as_int(g_dinv[s0]));
    if (p1 >= 0) g_srcw[p1] = make_int2(s1, __float_as_int(g_dinv[s1]));
}

// ---------------- aggregation from fp16 features -> fp16 A (4x unrolled MLP) ----------------
template <int D>
__global__ void aggregate_half_kernel(const __half* __restrict__ X, __half* __restrict__ A) {
    int node = (blockIdx.x * blockDim.x + threadIdx.x) >> 5;
    int lane = threadIdx.x & 31;
    if (node >= N_NODES) return;
    int beg = g_ptr[node], end = g_ptr[node + 1];
    float di = g_dinv[node];
    float selfw = di * di;
    float scale = 1.0f / g_deg[node];
    constexpr int V2 = D / 64;

    float2 acc[V2];
#pragma unroll
    for (int r = 0; r < V2; r++) acc[r] = make_float2(0.f, 0.f);

    auto rowptr = [&](int src) {
        return (const __half2*)(X + (long long)src * D) + lane * V2;
    };
    auto accum = [&](const __half2* hp, float w) {
#pragma unroll
        for (int r = 0; r < V2; r++) {
            float2 v = __half22float2(hp[r]);
            acc[r].x += w * v.x; acc[r].y += w * v.y;
        }
    };

    int p = beg;
    int end4 = beg + ((end - beg) & ~3);
    for (; p < end4; p += 4) {
        int2 sw0 = g_srcw[p], sw1 = g_srcw[p + 1], sw2 = g_srcw[p + 2], sw3 = g_srcw[p + 3];
        if constexpr (V2 == 4) {
            uint4 r0 = *(const uint4*)rowptr(sw0.x);
            uint4 r1 = *(const uint4*)rowptr(sw1.x);
            uint4 r2 = *(const uint4*)rowptr(sw2.x);
            uint4 r3 = *(const uint4*)rowptr(sw3.x);
            accum((const __half2*)&r0, __int_as_float(sw0.y));
            accum((const __half2*)&r1, __int_as_float(sw1.y));
            accum((const __half2*)&r2, __int_as_float(sw2.y));
            accum((const __half2*)&r3, __int_as_float(sw3.y));
        } else if constexpr (V2 == 2) {
            uint2 r0 = *(const uint2*)rowptr(sw0.x);
            uint2 r1 = *(const uint2*)rowptr(sw1.x);
            uint2 r2 = *(const uint2*)rowptr(sw2.x);
            uint2 r3 = *(const uint2*)rowptr(sw3.x);
            accum((const __half2*)&r0, __int_as_float(sw0.y));
            accum((const __half2*)&r1, __int_as_float(sw1.y));
            accum((const __half2*)&r2, __int_as_float(sw2.y));
            accum((const __half2*)&r3, __int_as_float(sw3.y));
        } else {
            __half2 r0 = *rowptr(sw0.x), r1 = *rowptr(sw1.x);
            __half2 r2 = *rowptr(sw2.x), r3 = *rowptr(sw3.x);
            accum(&r0, __int_as_float(sw0.y));
            accum(&r1, __int_as_float(sw1.y));
            accum(&r2, __int_as_float(sw2.y));
            accum(&r3, __int_as_float(sw3.y));
        }
    }
    for (; p < end; p++) {
        int2 sw = g_srcw[p];
        if constexpr (V2 == 4) {
            uint4 r0 = *(const uint4*)rowptr(sw.x);
            accum((const __half2*)&r0, __int_as_float(sw.y));
        } else if constexpr (V2 == 2) {
            uint2 r0 = *(const uint2*)rowptr(sw.x);
            accum((const __half2*)&r0, __int_as_float(sw.y));
        } else {
            __half2 r0 = *rowptr(sw.x);
            accum(&r0, __int_as_float(sw.y));
        }
    }

    const __half2* xi = (const __half2*)(X + (long long)node * D) + lane * V2;
    __half2* ao = (__half2*)(A + (long long)node * D) + lane * V2;
#pragma unroll
    for (int r = 0; r < V2; r++) {
        float2 s = __half22float2(xi[r]);
        ao[r] = __floats2half2_rn((di * acc[r].x + selfw * s.x) * scale,
                                  (di * acc[r].y + selfw * s.y) * scale);
    }
}

// layer-1 input aggregation (fp32 x, D=16): HALF-WARP per node, all lanes active
__global__ void aggregate16_kernel(const float* __restrict__ X, __half* __restrict__ A) {
    int gtid = blockIdx.x * blockDim.x + threadIdx.x;
    int node = gtid >> 4;
    int lidx = threadIdx.x & 15;
    if (node >= N_NODES) return;
    int beg = g_ptr[node], end = g_ptr[node + 1];
    float di = g_dinv[node];
    float acc = 0.f;
    int p = beg;
    int end4 = beg + ((end - beg) & ~3);
    for (; p < end4; p += 4) {
        int2 sw0 = g_srcw[p], sw1 = g_srcw[p + 1], sw2 = g_srcw[p + 2], sw3 = g_srcw[p + 3];
        float v0 = X[(long long)sw0.x * 16 + lidx];
        float v1 = X[(long long)sw1.x * 16 + lidx];
        float v2 = X[(long long)sw2.x * 16 + lidx];
        float v3 = X[(long long)sw3.x * 16 + lidx];
        acc += __int_as_float(sw0.y) * v0 + __int_as_float(sw1.y) * v1
             + __int_as_float(sw2.y) * v2 + __int_as_float(sw3.y) * v3;
    }
    for (; p < end; p++) {
        int2 sw = g_srcw[p];
        acc += __int_as_float(sw.y) * X[(long long)sw.x * 16 + lidx];
    }
    acc = (di * acc + di * di * X[(long long)node * 16 + lidx]) / g_deg[node];
    A[(long long)node * 32 + lidx]      = __float2half(acc);
    A[(long long)node * 32 + 16 + lidx] = __half(0);
}

// ---------------- fp16 tensor-core GEMM (HMMA m16n8k16, cp.async, ldmatrix) ----------------
__device__ __forceinline__ void mma_f16(float& c0, float& c1, float& c2, float& c3,
                                        uint32_t a0, uint32_t a1, uint32_t a2, uint32_t a3,
                                        uint32_t b0, uint32_t b1) {
    asm volatile(
        "mma.sync.aligned.m16n8k16.row.col.f32.f16.f16.f32 "
        "{%0,%1,%2,%3},{%4,%5,%6,%7},{%8,%9},{%0,%1,%2,%3};\n"
        : "+f"(c0), "+f"(c1), "+f"(c2), "+f"(c3)
        : "r"(a0), "r"(a1), "r"(a2), "r"(a3), "r"(b0), "r"(b1));
}

__device__ __forceinline__ void ldsm_x4(uint32_t& r0, uint32_t& r1, uint32_t& r2, uint32_t& r3,
                                        uint32_t addr) {
    asm volatile("ldmatrix.sync.aligned.m8n8.x4.shared.b16 {%0,%1,%2,%3}, [%4];"
                 : "=r"(r0), "=r"(r1), "=r"(r2), "=r"(r3) : "r"(addr));
}

__device__ __forceinline__ void ldsm_x4t(uint32_t& r0, uint32_t& r1, uint32_t& r2, uint32_t& r3,
                                         uint32_t addr) {
    asm volatile("ldmatrix.sync.aligned.m8n8.x4.trans.shared.b16 {%0,%1,%2,%3}, [%4];"
                 : "=r"(r0), "=r"(r1), "=r"(r2), "=r"(r3) : "r"(addr));
}

__device__ __forceinline__ void cp16(uint32_t dst, const void* src, bool pred) {
    int bytes = pred ? 16 : 0;
    asm volatile("cp.async.ca.shared.global [%0], [%1], 16, %2;\n"
                 :: "r"(dst), "l"(src), "r"(bytes));
}

// MODE: 1 = fp16 C, 2 = fused rowdot (no C)
template <int BN, int MODE>
__global__ __launch_bounds__(256)
void gemm_f16_kernel(const __half* __restrict__ A, const __half* __restrict__ B,
                     const float* __restrict__ bias, __half* __restrict__ Ch,
                     const float* __restrict__ w5, float* __restrict__ hpart,
                     int M, int K, int N) {
    constexpr int BM = 128, BK = 32;
    constexpr int ASTR = BK + 8;
    constexpr int BSTR = BN + 8;
    constexpr int WN = BN / 64, WM = 8 / WN, MT = BM / (WM * 16);

    __shared__ __half Ah[2][BM][ASTR];
    __shared__ __half Bh[2][BK][BSTR];

    int tid = threadIdx.x, lane = tid & 31, warp = tid >> 5;
    int warp_m = warp % WM, warp_n = warp / WM;
    int row0 = warp_m * (MT * 16), col0 = warp_n * 64;
    int rowBase = blockIdx.y * BM, colBase = blockIdx.x * BN;

    int ar = tid >> 2;
    int ac = (tid & 3) * 8;
    int br = tid / (BN / 8);
    int bc = (tid % (BN / 8)) * 8;

    auto issue = [&](int kt, int s) {
        int k0 = kt * BK;
#pragma unroll
        for (int i = 0; i < 2; i++) {
            int r = ar + i * 64;
            int gr = rowBase + r;
            bool ok = gr < M;
            const __half* src = A + (long long)(ok ? gr : 0) * K + k0 + ac;
            cp16((uint32_t)__cvta_generic_to_shared(&Ah[s][r][ac]), src, ok);
        }
        constexpr int RPW = 2048 / BN;
#pragma unroll
        for (int i = 0; i < BK / RPW; i++) {
            int r = br + i * RPW;
            const __half* src = B + (long long)(k0 + r) * N + colBase + bc;
            cp16((uint32_t)__cvta_generic_to_shared(&Bh[s][r][bc]), src, true);
        }
        asm volatile("cp.async.commit_group;\n");
    };

    float acc[MT][8][4];
#pragma unroll
    for (int mt = 0; mt < MT; mt++)
#pragma unroll
        for (int nt = 0; nt < 8; nt++)
#pragma unroll
            for (int q = 0; q < 4; q++) acc[mt][nt][q] = 0.f;

    int lr = lane >> 2, lc = lane & 3;
    int l8 = lane & 7;
    int lhalf = (lane >> 3) & 1;
    int lhi = lane >> 4;
    int KT = K / BK;

    issue(0, 0);
    for (int kt = 0; kt < KT; kt++) {
        int s = kt & 1;
        if (kt + 1 < KT) {
            issue(kt + 1, 1 - s);
            asm volatile("cp.async.wait_group 1;\n");
        } else {
            asm volatile("cp.async.wait_group 0;\n");
        }
        __syncthreads();
#pragma unroll
        for (int ks = 0; ks < 2; ks++) {
            int k16 = ks * 16;
            uint32_t bb[8][2];
#pragma unroll
            for (int pr = 0; pr < 4; pr++) {
                int n0 = col0 + pr * 16;
                uint32_t addr = (uint32_t)__cvta_generic_to_shared(
                    &Bh[s][k16 + l8 + lhalf * 8][n0 + lhi * 8]);
                ldsm_x4t(bb[2 * pr][0], bb[2 * pr][1], bb[2 * pr + 1][0], bb[2 * pr + 1][1], addr);
            }
#pragma unroll
            for (int mt = 0; mt < MT; mt++) {
                uint32_t a0, a1, a2, a3;
                uint32_t addr = (uint32_t)__cvta_generic_to_shared(
                    &Ah[s][row0 + mt * 16 + l8 + lhalf * 8][k16 + lhi * 8]);
                ldsm_x4(a0, a1, a2, a3, addr);
#pragma unroll
                for (int nt = 0; nt < 8; nt++)
                    mma_f16(acc[mt][nt][0], acc[mt][nt][1], acc[mt][nt][2], acc[mt][nt][3],
                            a0, a1, a2, a3, bb[nt][0], bb[nt][1]);
            }
        }
        __syncthreads();
    }

#pragma unroll
    for (int mt = 0; mt < MT; mt++) {
        int r1 = rowBase + row0 + mt * 16 + lr;
        int r2 = r1 + 8;
        float d1 = 0.f, d2 = 0.f;
#pragma unroll
        for (int nt = 0; nt < 8; nt++) {
            int c = colBase + col0 + nt * 8 + lc * 2;
            float bv0 = bias[c], bv1 = bias[c + 1];
            float v0 = fmaxf(acc[mt][nt][0] + bv0, 0.f);
            float v1 = fmaxf(acc[mt][nt][1] + bv1, 0.f);
            float v2 = fmaxf(acc[mt][nt][2] + bv0, 0.f);
            float v3 = fmaxf(acc[mt][nt][3] + bv1, 0.f);
            if constexpr (MODE == 2) {
                float w0 = w5[c], w1 = w5[c + 1];
                if (r1 < M) d1 += v0 * w0 + v1 * w1;
                if (r2 < M) d2 += v2 * w0 + v3 * w1;
            } else {
                if (r1 < M) *(__half2*)(Ch + (long long)r1 * N + c) = __floats2half2_rn(v0, v1);
                if (r2 < M) *(__half2*)(Ch + (long long)r2 * N + c) = __floats2half2_rn(v2, v3);
            }
        }
        if constexpr (MODE == 2) {
            d1 += __shfl_xor_sync(0xffffffffu, d1, 1);
            d1 += __shfl_xor_sync(0xffffffffu, d1, 2);
            d2 += __shfl_xor_sync(0xffffffffu, d2, 1);
            d2 += __shfl_xor_sync(0xffffffffu, d2, 2);
            int slot = blockIdx.x * WN + warp_n;
            if (lc == 0) {
                if (r1 < M) hpart[slot * N_NODES + r1] = d1;
                if (r2 < M) hpart[slot * N_NODES + r2] = d2;
            }
        }
    }
}

// ---------------- layer-5 reduce + add-aggregate + sigmoid ----------------
__global__ void hreduce_kernel(const float* __restrict__ hpart, float* __restrict__ h) {
    int i = blockIdx.x * blockDim.x + threadIdx.x;
    if (i < N_NODES) {
        float s = 0.f;
#pragma unroll
        for (int j = 0; j < 8; j++) s += hpart[j * N_NODES + i];
        h[i] = s;
    }
}

__global__ void final_agg_kernel(const float* __restrict__ h, const float* __restrict__ b5,
                                 float* __restrict__ out) {
    int i = blockIdx.x * blockDim.x + threadIdx.x;
    if (i >= N_NODES) return;
    float s = 0.f;
    int beg = g_ptr[i], end = g_ptr[i + 1];
    int p = beg;
    int end4 = beg + ((end - beg) & ~3);
    for (; p < end4; p += 4) {
        int2 sw0 = g_srcw[p], sw1 = g_srcw[p + 1], sw2 = g_srcw[p + 2], sw3 = g_srcw[p + 3];
        float h0 = h[sw0.x], h1 = h[sw1.x], h2 = h[sw2.x], h3 = h[sw3.x];
        s += __int_as_float(sw0.y) * h0 + __int_as_float(sw1.y) * h1
           + __int_as_float(sw2.y) * h2 + __int_as_float(sw3.y) * h3;
    }
    for (; p < end; p++) {
        int2 sw = g_srcw[p];
        s += __int_as_float(sw.y) * h[sw.x];
    }
    float di = g_dinv[i];
    float v = di * s + di * di * h[i] + b5[0];
    out[i] = 1.f / (1.f + expf(-v));
}

// ---------------- launch ----------------
extern "C" void kernel_launch(void* const* d_in, const int* in_sizes, int n_in,
                              void* d_out, int out_size) {
    const float* x  = (const float*)d_in[0];
    const void*  ei = d_in[1];
    const float* W1 = (const float*)d_in[2],  *b1 = (const float*)d_in[3];
    const float* W2 = (const float*)d_in[4],  *b2 = (const float*)d_in[5];
    const float* W3 = (const float*)d_in[6],  *b3 = (const float*)d_in[7];
    const float* W4 = (const float*)d_in[8],  *b4 = (const float*)d_in[9];
    const float* W5 = (const float*)d_in[10], *b5 = (const float*)d_in[11];
    float* out = (float*)d_out;

    __half *aggh, *featA, *featB, *w1h, *w2h, *w3h, *w4h;
    float *hpart, *hbuf;
    cudaGetSymbolAddress((void**)&aggh,  g_aggh);
    cudaGetSymbolAddress((void**)&featA, g_featA);
    cudaGetSymbolAddress((void**)&featB, g_featB);
    cudaGetSymbolAddress((void**)&w1h,   g_w1h);
    cudaGetSymbolAddress((void**)&w2h,   g_w2h);
    cudaGetSymbolAddress((void**)&w3h,   g_w3h);
    cudaGetSymbolAddress((void**)&w4h,   g_w4h);
    cudaGetSymbolAddress((void**)&hpart, g_hpart);
    cudaGetSymbolAddress((void**)&hbuf,  g_h);

    const int TPB = 256;
    int nodeBlocks = (N_NODES + TPB - 1) / TPB;
    int edgeBlocks2 = (N_EDGES / 2 + TPB - 1) / TPB;
    int warpNodeBlocks = (N_NODES * 32 + TPB - 1) / TPB;
    int halfNodeBlocks = (N_NODES * 16 + TPB - 1) / TPB;
    int prepBlocks = (174080 + TPB - 1) / TPB;
    int mBlocks = (N_NODES + 127) / 128;

    prep_kernel<<<prepBlocks, TPB>>>(ei, W1, W2, W3, W4);
    histo_kernel<<<edgeBlocks2, TPB>>>(ei);
    scan_node_init_kernel<<<1, 1024>>>();
    fill_kernel<<<edgeBlocks2, TPB>>>(ei);

    aggregate16_kernel<<<halfNodeBlocks, TPB>>>(x, aggh);
    gemm_f16_kernel<64, 1><<<dim3(1, mBlocks), 256>>>(aggh, w1h, b1, featA, nullptr, nullptr,
                                                      N_NODES, 32, 64);
    aggregate_half_kernel<64><<<warpNodeBlocks, TPB>>>(featA, aggh);
    gemm_f16_kernel<128, 1><<<dim3(1, mBlocks), 256>>>(aggh, w2h, b2, featB, nullptr, nullptr,
                                                       N_NODES, 64, 128);
    aggregate_half_kernel<128><<<warpNodeBlocks, TPB>>>(featB, aggh);
    gemm_f16_kernel<128, 1><<<dim3(2, mBlocks), 256>>>(aggh, w3h, b3, featA, nullptr, nullptr,
                                                       N_NODES, 128, 256);
    aggregate_half_kernel<256><<<warpNodeBlocks, TPB>>>(featA, aggh);
    gemm_f16_kernel<128, 2><<<dim3(4, mBlocks), 256>>>(aggh, w4h, b4, nullptr, W5, hpart,
                                                       N_NODES, 256, 512);
    hreduce_kernel<<<nodeBlocks, TPB>>>(hpart, hbuf);
    final_agg_kernel<<<nodeBlocks, TPB>>>(hbuf, b5, out);
}

// round 17
// speedup vs baseline: 1.1421x; 1.0710x over previous
#include <cuda_runtime.h>
#include <cuda_fp16.h>
#include <math.h>
#include <stdint.h>

#define N_NODES 20000
#define N_EDGES 320000

// ---------------- device scratch ----------------
__device__ int   g_e64;
__device__ int   g_cnt[N_NODES];
__device__ int   g_ptr[N_NODES + 1];
__device__ int   g_rank[N_EDGES];          // edge's rank within its dst bucket (from histo)
__device__ __align__(16) int2  g_srcw[N_EDGES];
__device__ float g_deg[N_NODES];
__device__ float g_dinv[N_NODES];
__device__ __align__(256) __half g_aggh[N_NODES * 256];
__device__ __align__(256) __half g_featA[N_NODES * 256];
__device__ __align__(256) __half g_featB[N_NODES * 128];
__device__ __align__(16) __half g_w1h[32 * 64];
__device__ __align__(16) __half g_w2h[64 * 128];
__device__ __align__(16) __half g_w3h[128 * 256];
__device__ __align__(16) __half g_w4h[256 * 512];
__device__ float g_hpart[8 * N_NODES];
__device__ float g_h[N_NODES];

__device__ __forceinline__ int edge_at(const void* e, long long idx) {
    if (g_e64) return (int)((const long long*)e)[idx];
    return ((const int*)e)[idx];
}

// ---------------- prep: zero cnt + dtype detect + weight fp16 conversion ----------------
__global__ void prep_kernel(const void* e, const float* __restrict__ W1,
                            const float* __restrict__ W2, const float* __restrict__ W3,
                            const float* __restrict__ W4) {
    int i = blockIdx.x * blockDim.x + threadIdx.x;
    if (i < N_NODES) g_cnt[i] = 0;
    if (i == 0) {
        const long long* p = (const long long*)e;
        bool ok = true;
#pragma unroll
        for (int k = 0; k < 8; k++) {
            long long v = p[k];
            if (v < 0 || v >= N_NODES) ok = false;
        }
        g_e64 = ok ? 1 : 0;
    }
    if (i < 2048) {
        int k = i >> 6, n = i & 63;
        g_w1h[i] = __float2half(k < 16 ? W1[k * 64 + n] : 0.f);
    } else if (i < 2048 + 8192) {
        int j = i - 2048;  g_w2h[j] = __float2half(W2[j]);
    } else if (i < 2048 + 8192 + 32768) {
        int j = i - 10240; g_w3h[j] = __float2half(W3[j]);
    } else if (i < 2048 + 8192 + 32768 + 131072) {
        int j = i - 43008; g_w4h[j] = __float2half(W4[j]);
    }
}

// histogram; also records each edge's rank within its destination bucket
__global__ void histo_kernel(const void* e) {
    int i0 = (blockIdx.x * blockDim.x + threadIdx.x) * 2;
    if (i0 < N_EDGES) {
        int d0 = edge_at(e, (long long)N_EDGES + i0);
        g_rank[i0] = atomicAdd(&g_cnt[d0], 1);
    }
    if (i0 + 1 < N_EDGES) {
        int d1 = edge_at(e, (long long)N_EDGES + i0 + 1);
        g_rank[i0 + 1] = atomicAdd(&g_cnt[d1], 1);
    }
}

__global__ void scan_node_init_kernel() {
    const int C = (N_NODES + 1023) / 1024;   // 20
    int t = threadIdx.x;
    int base = t * C;
    int local[C];
    int sum = 0;
#pragma unroll
    for (int c = 0; c < C; c++) {
        int i = base + c;
        int v = (i < N_NODES) ? g_cnt[i] : 0;
        sum += v;
        local[c] = sum;
    }
    int lane = t & 31, wid = t >> 5;
    int incl = sum;
#pragma unroll
    for (int o = 1; o < 32; o <<= 1) {
        int y = __shfl_up_sync(0xffffffffu, incl, o);
        if (lane >= o) incl += y;
    }
    __shared__ int ws[32];
    if (lane == 31) ws[wid] = incl;
    __syncthreads();
    if (wid == 0) {
        int v = ws[lane];
        int iv = v;
#pragma unroll
        for (int o = 1; o < 32; o <<= 1) {
            int y = __shfl_up_sync(0xffffffffu, iv, o);
            if (lane >= o) iv += y;
        }
        ws[lane] = iv - v;
    }
    __syncthreads();
    int offset = ws[wid] + (incl - sum);
    if (t == 0) g_ptr[0] = 0;
#pragma unroll
    for (int c = 0; c < C; c++) {
        int i = base + c;
        if (i >= N_NODES) break;
        g_ptr[i + 1] = offset + local[c];
        int v = local[c] - (c ? local[c - 1] : 0);
        float d = (float)(v + 1);
        g_deg[i] = d;
        g_dinv[i] = rsqrtf(d);
    }
}

// atomic-free fill: position = ptr[dst] + rank (precomputed in histo)
__global__ void fill_kernel(const void* e) {
    int i0 = (blockIdx.x * blockDim.x + threadIdx.x) * 2;
    if (i0 < N_EDGES) {
        int s0 = edge_at(e, i0);
        int d0 = edge_at(e, (long long)N_EDGES + i0);
        int pos = g_ptr[d0] + g_rank[i0];
        g_srcw[pos] = make_int2(s0, __float_as_int(g_dinv[s0]));
    }
    if (i0 + 1 < N_EDGES) {
        int s1 = edge_at(e, i0 + 1);
        int d1 = edge_at(e, (long long)N_EDGES + i0 + 1);
        int pos = g_ptr[d1] + g_rank[i0 + 1];
        g_srcw[pos] = make_int2(s1, __float_as_int(g_dinv[s1]));
    }
}

// ---------------- aggregation from fp16 features -> fp16 A (4x unrolled MLP) ----------------
template <int D>
__global__ void aggregate_half_kernel(const __half* __restrict__ X, __half* __restrict__ A) {
    int node = (blockIdx.x * blockDim.x + threadIdx.x) >> 5;
    int lane = threadIdx.x & 31;
    if (node >= N_NODES) return;
    int beg = g_ptr[node], end = g_ptr[node + 1];
    float di = g_dinv[node];
    float selfw = di * di;
    float scale = 1.0f / g_deg[node];
    constexpr int V2 = D / 64;

    float2 acc[V2];
#pragma unroll
    for (int r = 0; r < V2; r++) acc[r] = make_float2(0.f, 0.f);

    auto rowptr = [&](int src) {
        return (const __half2*)(X + (long long)src * D) + lane * V2;
    };
    auto accum = [&](const __half2* hp, float w) {
#pragma unroll
        for (int r = 0; r < V2; r++) {
            float2 v = __half22float2(hp[r]);
            acc[r].x += w * v.x; acc[r].y += w * v.y;
        }
    };

    int p = beg;
    int end4 = beg + ((end - beg) & ~3);
    for (; p < end4; p += 4) {
        int2 sw0 = g_srcw[p], sw1 = g_srcw[p + 1], sw2 = g_srcw[p + 2], sw3 = g_srcw[p + 3];
        if constexpr (V2 == 4) {
            uint4 r0 = *(const uint4*)rowptr(sw0.x);
            uint4 r1 = *(const uint4*)rowptr(sw1.x);
            uint4 r2 = *(const uint4*)rowptr(sw2.x);
            uint4 r3 = *(const uint4*)rowptr(sw3.x);
            accum((const __half2*)&r0, __int_as_float(sw0.y));
            accum((const __half2*)&r1, __int_as_float(sw1.y));
            accum((const __half2*)&r2, __int_as_float(sw2.y));
            accum((const __half2*)&r3, __int_as_float(sw3.y));
        } else if constexpr (V2 == 2) {
            uint2 r0 = *(const uint2*)rowptr(sw0.x);
            uint2 r1 = *(const uint2*)rowptr(sw1.x);
            uint2 r2 = *(const uint2*)rowptr(sw2.x);
            uint2 r3 = *(const uint2*)rowptr(sw3.x);
            accum((const __half2*)&r0, __int_as_float(sw0.y));
            accum((const __half2*)&r1, __int_as_float(sw1.y));
            accum((const __half2*)&r2, __int_as_float(sw2.y));
            accum((const __half2*)&r3, __int_as_float(sw3.y));
        } else {
            __half2 r0 = *rowptr(sw0.x), r1 = *rowptr(sw1.x);
            __half2 r2 = *rowptr(sw2.x), r3 = *rowptr(sw3.x);
            accum(&r0, __int_as_float(sw0.y));
            accum(&r1, __int_as_float(sw1.y));
            accum(&r2, __int_as_float(sw2.y));
            accum(&r3, __int_as_float(sw3.y));
        }
    }
    for (; p < end; p++) {
        int2 sw = g_srcw[p];
        if constexpr (V2 == 4) {
            uint4 r0 = *(const uint4*)rowptr(sw.x);
            accum((const __half2*)&r0, __int_as_float(sw.y));
        } else if constexpr (V2 == 2) {
            uint2 r0 = *(const uint2*)rowptr(sw.x);
            accum((const __half2*)&r0, __int_as_float(sw.y));
        } else {
            __half2 r0 = *rowptr(sw.x);
            accum(&r0, __int_as_float(sw.y));
        }
    }

    const __half2* xi = (const __half2*)(X + (long long)node * D) + lane * V2;
    __half2* ao = (__half2*)(A + (long long)node * D) + lane * V2;
#pragma unroll
    for (int r = 0; r < V2; r++) {
        float2 s = __half22float2(xi[r]);
        ao[r] = __floats2half2_rn((di * acc[r].x + selfw * s.x) * scale,
                                  (di * acc[r].y + selfw * s.y) * scale);
    }
}

// layer-1 input aggregation (fp32 x, D=16): half-warp per node, all lanes active
__global__ void aggregate16_kernel(const float* __restrict__ X, __half* __restrict__ A) {
    int gtid = blockIdx.x * blockDim.x + threadIdx.x;
    int node = gtid >> 4;
    int lidx = threadIdx.x & 15;
    if (node >= N_NODES) return;
    int beg = g_ptr[node], end = g_ptr[node + 1];
    float di = g_dinv[node];
    float acc = 0.f;
    int p = beg;
    int end4 = beg + ((end - beg) & ~3);
    for (; p < end4; p += 4) {
        int2 sw0 = g_srcw[p], sw1 = g_srcw[p + 1], sw2 = g_srcw[p + 2], sw3 = g_srcw[p + 3];
        float v0 = X[(long long)sw0.x * 16 + lidx];
        float v1 = X[(long long)sw1.x * 16 + lidx];
        float v2 = X[(long long)sw2.x * 16 + lidx];
        float v3 = X[(long long)sw3.x * 16 + lidx];
        acc += __int_as_float(sw0.y) * v0 + __int_as_float(sw1.y) * v1
             + __int_as_float(sw2.y) * v2 + __int_as_float(sw3.y) * v3;
    }
    for (; p < end; p++) {
        int2 sw = g_srcw[p];
        acc += __int_as_float(sw.y) * X[(long long)sw.x * 16 + lidx];
    }
    acc = (di * acc + di * di * X[(long long)node * 16 + lidx]) / g_deg[node];
    A[(long long)node * 32 + lidx]      = __float2half(acc);
    A[(long long)node * 32 + 16 + lidx] = __half(0);
}

// ---------------- fp16 tensor-core GEMM (HMMA m16n8k16, cp.async, ldmatrix) ----------------
__device__ __forceinline__ void mma_f16(float& c0, float& c1, float& c2, float& c3,
                                        uint32_t a0, uint32_t a1, uint32_t a2, uint32_t a3,
                                        uint32_t b0, uint32_t b1) {
    asm volatile(
        "mma.sync.aligned.m16n8k16.row.col.f32.f16.f16.f32 "
        "{%0,%1,%2,%3},{%4,%5,%6,%7},{%8,%9},{%0,%1,%2,%3};\n"
        : "+f"(c0), "+f"(c1), "+f"(c2), "+f"(c3)
        : "r"(a0), "r"(a1), "r"(a2), "r"(a3), "r"(b0), "r"(b1));
}

__device__ __forceinline__ void ldsm_x4(uint32_t& r0, uint32_t& r1, uint32_t& r2, uint32_t& r3,
                                        uint32_t addr) {
    asm volatile("ldmatrix.sync.aligned.m8n8.x4.shared.b16 {%0,%1,%2,%3}, [%4];"
                 : "=r"(r0), "=r"(r1), "=r"(r2), "=r"(r3) : "r"(addr));
}

__device__ __forceinline__ void ldsm_x4t(uint32_t& r0, uint32_t& r1, uint32_t& r2, uint32_t& r3,
                                         uint32_t addr) {
    asm volatile("ldmatrix.sync.aligned.m8n8.x4.trans.shared.b16 {%0,%1,%2,%3}, [%4];"
                 : "=r"(r0), "=r"(r1), "=r"(r2), "=r"(r3) : "r"(addr));
}

__device__ __forceinline__ void cp16(uint32_t dst, const void* src, bool pred) {
    int bytes = pred ? 16 : 0;
    asm volatile("cp.async.ca.shared.global [%0], [%1], 16, %2;\n"
                 :: "r"(dst), "l"(src), "r"(bytes));
}

// MODE: 1 = fp16 C, 2 = fused rowdot (no C)
template <int BN, int MODE>
__global__ __launch_bounds__(256)
void gemm_f16_kernel(const __half* __restrict__ A, const __half* __restrict__ B,
                     const float* __restrict__ bias, __half* __restrict__ Ch,
                     const float* __restrict__ w5, float* __restrict__ hpart,
                     int M, int K, int N) {
    constexpr int BM = 128, BK = 32;
    constexpr int ASTR = BK + 8;
    constexpr int BSTR = BN + 8;
    constexpr int WN = BN / 64, WM = 8 / WN, MT = BM / (WM * 16);

    __shared__ __half Ah[2][BM][ASTR];
    __shared__ __half Bh[2][BK][BSTR];

    int tid = threadIdx.x, lane = tid & 31, warp = tid >> 5;
    int warp_m = warp % WM, warp_n = warp / WM;
    int row0 = warp_m * (MT * 16), col0 = warp_n * 64;
    int rowBase = blockIdx.y * BM, colBase = blockIdx.x * BN;

    int ar = tid >> 2;
    int ac = (tid & 3) * 8;
    int br = tid / (BN / 8);
    int bc = (tid % (BN / 8)) * 8;

    auto issue = [&](int kt, int s) {
        int k0 = kt * BK;
#pragma unroll
        for (int i = 0; i < 2; i++) {
            int r = ar + i * 64;
            int gr = rowBase + r;
            bool ok = gr < M;
            const __half* src = A + (long long)(ok ? gr : 0) * K + k0 + ac;
            cp16((uint32_t)__cvta_generic_to_shared(&Ah[s][r][ac]), src, ok);
        }
        constexpr int RPW = 2048 / BN;
#pragma unroll
        for (int i = 0; i < BK / RPW; i++) {
            int r = br + i * RPW;
            const __half* src = B + (long long)(k0 + r) * N + colBase + bc;
            cp16((uint32_t)__cvta_generic_to_shared(&Bh[s][r][bc]), src, true);
        }
        asm volatile("cp.async.commit_group;\n");
    };

    float acc[MT][8][4];
#pragma unroll
    for (int mt = 0; mt < MT; mt++)
#pragma unroll
        for (int nt = 0; nt < 8; nt++)
#pragma unroll
            for (int q = 0; q < 4; q++) acc[mt][nt][q] = 0.f;

    int lr = lane >> 2, lc = lane & 3;
    int l8 = lane & 7;
    int lhalf = (lane >> 3) & 1;
    int lhi = lane >> 4;
    int KT = K / BK;

    issue(0, 0);
    for (int kt = 0; kt < KT; kt++) {
        int s = kt & 1;
        if (kt + 1 < KT) {
            issue(kt + 1, 1 - s);
            asm volatile("cp.async.wait_group 1;\n");
        } else {
            asm volatile("cp.async.wait_group 0;\n");
        }
        __syncthreads();
#pragma unroll
        for (int ks = 0; ks < 2; ks++) {
            int k16 = ks * 16;
            uint32_t bb[8][2];
#pragma unroll
            for (int pr = 0; pr < 4; pr++) {
                int n0 = col0 + pr * 16;
                uint32_t addr = (uint32_t)__cvta_generic_to_shared(
                    &Bh[s][k16 + l8 + lhalf * 8][n0 + lhi * 8]);
                ldsm_x4t(bb[2 * pr][0], bb[2 * pr][1], bb[2 * pr + 1][0], bb[2 * pr + 1][1], addr);
            }
#pragma unroll
            for (int mt = 0; mt < MT; mt++) {
                uint32_t a0, a1, a2, a3;
                uint32_t addr = (uint32_t)__cvta_generic_to_shared(
                    &Ah[s][row0 + mt * 16 + l8 + lhalf * 8][k16 + lhi * 8]);
                ldsm_x4(a0, a1, a2, a3, addr);
#pragma unroll
                for (int nt = 0; nt < 8; nt++)
                    mma_f16(acc[mt][nt][0], acc[mt][nt][1], acc[mt][nt][2], acc[mt][nt][3],
                            a0, a1, a2, a3, bb[nt][0], bb[nt][1]);
            }
        }
        __syncthreads();
    }

#pragma unroll
    for (int mt = 0; mt < MT; mt++) {
        int r1 = rowBase + row0 + mt * 16 + lr;
        int r2 = r1 + 8;
        float d1 = 0.f, d2 = 0.f;
#pragma unroll
        for (int nt = 0; nt < 8; nt++) {
            int c = colBase + col0 + nt * 8 + lc * 2;
            float bv0 = bias[c], bv1 = bias[c + 1];
            float v0 = fmaxf(acc[mt][nt][0] + bv0, 0.f);
            float v1 = fmaxf(acc[mt][nt][1] + bv1, 0.f);
            float v2 = fmaxf(acc[mt][nt][2] + bv0, 0.f);
            float v3 = fmaxf(acc[mt][nt][3] + bv1, 0.f);
            if constexpr (MODE == 2) {
                float w0 = w5[c], w1 = w5[c + 1];
                if (r1 < M) d1 += v0 * w0 + v1 * w1;
                if (r2 < M) d2 += v2 * w0 + v3 * w1;
            } else {
                if (r1 < M) *(__half2*)(Ch + (long long)r1 * N + c) = __floats2half2_rn(v0, v1);
                if (r2 < M) *(__half2*)(Ch + (long long)r2 * N + c) = __floats2half2_rn(v2, v3);
            }
        }
        if constexpr (MODE == 2) {
            d1 += __shfl_xor_sync(0xffffffffu, d1, 1);
            d1 += __shfl_xor_sync(0xffffffffu, d1, 2);
            d2 += __shfl_xor_sync(0xffffffffu, d2, 1);
            d2 += __shfl_xor_sync(0xffffffffu, d2, 2);
            int slot = blockIdx.x * WN + warp_n;
            if (lc == 0) {
                if (r1 < M) hpart[slot * N_NODES + r1] = d1;
                if (r2 < M) hpart[slot * N_NODES + r2] = d2;
            }
        }
    }
}

// ---------------- layer-5 reduce + add-aggregate + sigmoid ----------------
__global__ void hreduce_kernel(const float* __restrict__ hpart, float* __restrict__ h) {
    int i = blockIdx.x * blockDim.x + threadIdx.x;
    if (i < N_NODES) {
        float s = 0.f;
#pragma unroll
        for (int j = 0; j < 8; j++) s += hpart[j * N_NODES + i];
        h[i] = s;
    }
}

__global__ void final_agg_kernel(const float* __restrict__ h, const float* __restrict__ b5,
                                 float* __restrict__ out) {
    int i = blockIdx.x * blockDim.x + threadIdx.x;
    if (i >= N_NODES) return;
    float s = 0.f;
    int beg = g_ptr[i], end = g_ptr[i + 1];
    int p = beg;
    int end4 = beg + ((end - beg) & ~3);
    for (; p < end4; p += 4) {
        int2 sw0 = g_srcw[p], sw1 = g_srcw[p + 1], sw2 = g_srcw[p + 2], sw3 = g_srcw[p + 3];
        float h0 = h[sw0.x], h1 = h[sw1.x], h2 = h[sw2.x], h3 = h[sw3.x];
        s += __int_as_float(sw0.y) * h0 + __int_as_float(sw1.y) * h1
           + __int_as_float(sw2.y) * h2 + __int_as_float(sw3.y) * h3;
    }
    for (; p < end; p++) {
        int2 sw = g_srcw[p];
        s += __int_as_float(sw.y) * h[sw.x];
    }
    float di = g_dinv[i];
    float v = di * s + di * di * h[i] + b5[0];
    out[i] = 1.f / (1.f + expf(-v));
}

// ---------------- launch ----------------
extern "C" void kernel_launch(void* const* d_in, const int* in_sizes, int n_in,
                              void* d_out, int out_size) {
    const float* x  = (const float*)d_in[0];
    const void*  ei = d_in[1];
    const float* W1 = (const float*)d_in[2],  *b1 = (const float*)d_in[3];
    const float* W2 = (const float*)d_in[4],  *b2 = (const float*)d_in[5];
    const float* W3 = (const float*)d_in[6],  *b3 = (const float*)d_in[7];
    const float* W4 = (const float*)d_in[8],  *b4 = (const float*)d_in[9];
    const float* W5 = (const float*)d_in[10], *b5 = (const float*)d_in[11];
    float* out = (float*)d_out;

    __half *aggh, *featA, *featB, *w1h, *w2h, *w3h, *w4h;
    float *hpart, *hbuf;
    cudaGetSymbolAddress((void**)&aggh,  g_aggh);
    cudaGetSymbolAddress((void**)&featA, g_featA);
    cudaGetSymbolAddress((void**)&featB, g_featB);
    cudaGetSymbolAddress((void**)&w1h,   g_w1h);
    cudaGetSymbolAddress((void**)&w2h,   g_w2h);
    cudaGetSymbolAddress((void**)&w3h,   g_w3h);
    cudaGetSymbolAddress((void**)&w4h,   g_w4h);
    cudaGetSymbolAddress((void**)&hpart, g_hpart);
    cudaGetSymbolAddress((void**)&hbuf,  g_h);

    const int TPB = 256;
    int nodeBlocks = (N_NODES + TPB - 1) / TPB;
    int edgeBlocks2 = (N_EDGES / 2 + TPB - 1) / TPB;
    int warpNodeBlocks = (N_NODES * 32 + TPB - 1) / TPB;
    int halfNodeBlocks = (N_NODES * 16 + TPB - 1) / TPB;
    int prepBlocks = (174080 + TPB - 1) / TPB;
    int mBlocks = (N_NODES + 127) / 128;

    prep_kernel<<<prepBlocks, TPB>>>(ei, W1, W2, W3, W4);
    histo_kernel<<<edgeBlocks2, TPB>>>(ei);
    scan_node_init_kernel<<<1, 1024>>>();
    fill_kernel<<<edgeBlocks2, TPB>>>(ei);

    aggregate16_kernel<<<halfNodeBlocks, TPB>>>(x, aggh);
    gemm_f16_kernel<64, 1><<<dim3(1, mBlocks), 256>>>(aggh, w1h, b1, featA, nullptr, nullptr,
                                                      N_NODES, 32, 64);
    aggregate_half_kernel<64><<<warpNodeBlocks, TPB>>>(featA, aggh);
    gemm_f16_kernel<128, 1><<<dim3(1, mBlocks), 256>>>(aggh, w2h, b2, featB, nullptr, nullptr,
                                                       N_NODES, 64, 128);
    aggregate_half_kernel<128><<<warpNodeBlocks, TPB>>>(featB, aggh);
    gemm_f16_kernel<128, 1><<<dim3(2, mBlocks), 256>>>(aggh, w3h, b3, featA, nullptr, nullptr,
                                                       N_NODES, 128, 256);
    aggregate_half_kernel<256><<<warpNodeBlocks, TPB>>>(featA, aggh);
    gemm_f16_kernel<128, 2><<<dim3(4, mBlocks), 256>>>(aggh, w4h, b4, nullptr, W5, hpart,
                                                       N_NODES, 256, 512);
    hreduce_kernel<<<nodeBlocks, TPB>>>(hpart, hbuf);
    final_agg_kernel<<<nodeBlocks, TPB>>>(hbuf, b5, out);
}